// round 14
// baseline (speedup 1.0000x reference)
#include <cuda_runtime.h>
#include <cuda_bf16.h>
#include <math.h>

#define T_   256
#define B_   64
#define H_   256
#define HID_ 512
#define NTAG 34
#define G4H  1024

__device__ float d_X0[T_*B_*256];
__device__ float d_H1[T_*B_*HID_];
__device__ float d_H2[T_*B_*HID_];
__device__ float d_HC[T_*B_*HID_];     // scan output: [t][dir*256+kh][b]
__device__ float d_XP[2u*T_*B_*G4H];   // [dir][t][gate n (1024)][b (64)]
__device__ float d_EM[T_*B_*NTAG];
__device__ float d_hbuf[2*2*H_*B_];    // [dir][pingpong][k][b]
__device__ volatile int g_flag[2][64*32];
__device__ volatile int g_rel[2][32];

#define FMA2(d, a, b) asm("fma.rn.f32x2 %0, %1, %2, %0;" : "+l"(d) : "l"(a), "l"(b))

__device__ __forceinline__ float2 u64_as_f2(unsigned long long v) {
    float2 r; asm("mov.b64 {%0, %1}, %2;" : "=f"(r.x), "=f"(r.y) : "l"(v)); return r;
}

__device__ __forceinline__ void flag_barrier(int dir, int myid, int val) {
    __syncthreads();
    if (threadIdx.x == 0) { __threadfence(); g_flag[dir][myid*32] = val; }
    if (myid == 0) {
        if (threadIdx.x < 64) { while (g_flag[dir][threadIdx.x*32] < val) { } }
        __syncthreads();
        if (threadIdx.x == 0) { __threadfence(); g_rel[dir][0] = val; }
    }
    if (threadIdx.x == 0) { while (g_rel[dir][0] < val) { } }
    __syncthreads();
}

__global__ void zero_flags() {
    int i = blockIdx.x * 256 + threadIdx.x;
    if (i < 64*32) { g_flag[0][i] = 0; g_flag[1][i] = 0; }
    if (i < 32)    { g_rel[0][i] = 0;  g_rel[1][i] = 0; }
}

__global__ void embed_kernel(const int* __restrict__ x, const float* __restrict__ embed) {
    size_t idx = (size_t)blockIdx.x * 256 + threadIdx.x;
    int row = (int)(idx >> 6);
    int c   = (int)(idx & 63);
    int tok = x[row];
    ((float4*)d_X0)[idx] = ((const float4*)embed)[(size_t)tok * 64 + c];
}

// d_HC [t][c][b] -> (which ? d_H2 : d_H1) [m=t*64+b][c]
// NOTE: device globals referenced INSIDE the kernel (host-passed __device__
// symbols silently write the host shadow via HMM on GB300 — R11/R12 bug).
__global__ void transpose_h(int which) {
    const float* __restrict__ src = d_HC;
    float* __restrict__ dst = which ? d_H2 : d_H1;
    const int t  = blockIdx.y;
    const int c0 = blockIdx.x * 32;
    const int tid = threadIdx.x;
    __shared__ float tile[32][65];
#pragma unroll
    for (int i = 0; i < 8; i++) {
        int idx = tid + i*256;
        int cc = idx >> 6, b = idx & 63;
        tile[cc][b] = src[((size_t)t*512 + c0 + cc)*64 + b];
    }
    __syncthreads();
#pragma unroll
    for (int i = 0; i < 8; i++) {
        int idx = tid + i*256;
        int b = idx >> 5, cc = idx & 31;
        dst[((size_t)t*64 + b)*512 + c0 + cc] = tile[cc][b];
    }
}

// Transposed output: C[t][n][b] = A[m,:].W[n,:] + bi[n] + bh[n]
__global__ __launch_bounds__(256, 2)
void sgemm_bias(int asel, const float* __restrict__ Wbase,
                const float* __restrict__ bi_base, const float* __restrict__ bh_base, int K) {
    const float* A = asel ? d_H1 : d_X0;
    const int z = blockIdx.z;
    const float* W  = Wbase + (size_t)z * 1024 * K;
    const float* bi = bi_base + (size_t)z * 1024;
    const float* bh = bh_base + (size_t)z * 1024;
    float* C = d_XP + (size_t)z * (T_*B_*G4H);

    __shared__ float2 As2[8][128];
    __shared__ float  Bs[8][128];

    const int tid = threadIdx.x;
    const int m0 = blockIdx.y * 128;
    const int n0 = blockIdx.x * 128;

    const int lm  = tid >> 1;
    const int lk4 = (tid & 1) * 4;
    const float* aptr = A + (size_t)(m0 + lm) * K + lk4;
    const float* wptr = W + (size_t)(n0 + lm) * K + lk4;

    const int my = tid >> 3;
    const int tx = tid & 7;

    unsigned long long acc[4][8];
#pragma unroll
    for (int i = 0; i < 4; i++)
#pragma unroll
        for (int p = 0; p < 8; p++) acc[i][p] = 0ULL;

    for (int kt = 0; kt < (K >> 3); kt++) {
        float4 av = *(const float4*)aptr;
        float4 wv = *(const float4*)wptr;
        aptr += 8; wptr += 8;
        __syncthreads();
        As2[lk4+0][lm] = make_float2(av.x, av.x);
        As2[lk4+1][lm] = make_float2(av.y, av.y);
        As2[lk4+2][lm] = make_float2(av.z, av.z);
        As2[lk4+3][lm] = make_float2(av.w, av.w);
        Bs[lk4+0][lm] = wv.x; Bs[lk4+1][lm] = wv.y; Bs[lk4+2][lm] = wv.z; Bs[lk4+3][lm] = wv.w;
        __syncthreads();
#pragma unroll
        for (int kk = 0; kk < 8; kk++) {
            ulonglong2 a01 = *(const ulonglong2*)&As2[kk][my*4];
            ulonglong2 a23 = *(const ulonglong2*)&As2[kk][my*4 + 2];
            unsigned long long aD[4] = {a01.x, a01.y, a23.x, a23.y};
            ulonglong2 b0 = *(const ulonglong2*)&Bs[kk][tx*4];
            ulonglong2 b1 = *(const ulonglong2*)&Bs[kk][32 + tx*4];
            ulonglong2 b2 = *(const ulonglong2*)&Bs[kk][64 + tx*4];
            ulonglong2 b3 = *(const ulonglong2*)&Bs[kk][96 + tx*4];
#pragma unroll
            for (int i = 0; i < 4; i++) {
                FMA2(acc[i][0], aD[i], b0.x); FMA2(acc[i][1], aD[i], b0.y);
                FMA2(acc[i][2], aD[i], b1.x); FMA2(acc[i][3], aD[i], b1.y);
                FMA2(acc[i][4], aD[i], b2.x); FMA2(acc[i][5], aD[i], b2.y);
                FMA2(acc[i][6], aD[i], b3.x); FMA2(acc[i][7], aD[i], b3.y);
            }
        }
    }
    const int tt  = (m0 >> 6) + (my >> 4);
    const int b0e = (my & 15) * 4;
    float* Ct = C + (size_t)tt * (G4H*64);
#pragma unroll
    for (int p = 0; p < 8; p++) {
        int n = n0 + (p >> 1)*32 + tx*4 + (p & 1)*2;
        float bias0 = bi[n] + bh[n];
        float bias1 = bi[n+1] + bh[n+1];
        float2 t0 = u64_as_f2(acc[0][p]);
        float2 t1 = u64_as_f2(acc[1][p]);
        float2 t2 = u64_as_f2(acc[2][p]);
        float2 t3 = u64_as_f2(acc[3][p]);
        *(float4*)(Ct + (size_t)n*64 + b0e) =
            make_float4(t0.x+bias0, t1.x+bias0, t2.x+bias0, t3.x+bias0);
        *(float4*)(Ct + (size_t)(n+1)*64 + b0e) =
            make_float4(t0.y+bias1, t1.y+bias1, t2.y+bias1, t3.y+bias1);
    }
}

__device__ __forceinline__ float sigf(float v) { return 1.f / (1.f + expf(-v)); }

// Persistent scan (R10-proven core), coalesced d_HC output.
__global__ __launch_bounds__(256, 1)
void lstm_scan(const float* __restrict__ Whh_base, const int* __restrict__ xtok) {
    extern __shared__ float sm[];
    float*  hs  = sm;
    float2* Wt2 = (float2*)(sm + 16384);
    float*  Pf  = sm + 16384 + 8192;

    const int tid  = threadIdx.x;
    const int dir  = blockIdx.x >> 6;
    const int myid = blockIdx.x & 63;
    const int u0   = myid << 2;
    const float* Whh = Whh_base + (size_t)dir * (G4H * H_);

    for (int idx = tid; idx < 4096; idx += 256) {
        int k = idx >> 4, col = idx & 15;
        int g = col >> 2, u = col & 3;
        float w = Whh[(size_t)(g*256 + u0 + u) * 256 + k];
        Wt2[k*16 + col] = make_float2(w, w);
    }

    const int btile = tid & 15;
    const int g     = (tid >> 4) & 3;
    const int kq    = tid >> 6;
    const int eb    = tid & 63;
    const int eu    = tid >> 6;
    const int kh    = u0 + eu;

    d_hbuf[(size_t)(dir*2 + 0) * (H_*B_) + kh*64 + eb] = 0.f;
    float c_reg = 0.f;
    flag_barrier(dir, myid, 1);

    for (int s = 0; s < T_; s++) {
        const int t   = dir ? (T_-1-s) : s;
        const int cur = s & 1;
        const float4* hq4 = (const float4*)(d_hbuf + (size_t)(dir*2 + cur) * (H_*B_));
        float4* hs4 = (float4*)hs;

#pragma unroll
        for (int i = 0; i < 16; i++)
            hs4[tid + (i << 8)] = __ldcg(&hq4[tid + (i << 8)]);

        const float* xpt = d_XP + (size_t)(dir*T_ + t) * (G4H*64);
        float xp0 = __ldcg(xpt + (size_t)(0*256 + kh)*64 + eb);
        float xp1 = __ldcg(xpt + (size_t)(1*256 + kh)*64 + eb);
        float xp2 = __ldcg(xpt + (size_t)(2*256 + kh)*64 + eb);
        float xp3 = __ldcg(xpt + (size_t)(3*256 + kh)*64 + eb);
        int   tok = __ldg(&xtok[t*64 + eb]);
        __syncthreads();

        unsigned long long acc[8];
#pragma unroll
        for (int i = 0; i < 8; i++) acc[i] = 0ULL;
        const int kbase = kq << 6;
#pragma unroll 8
        for (int kk = 0; kk < 64; kk++) {
            int k = kbase + kk;
            ulonglong2 hp = *(const ulonglong2*)&hs[(k << 6) + (btile << 2)];
            ulonglong2 wa = *(const ulonglong2*)&Wt2[k*16 + (g << 2)];
            ulonglong2 wb = *(const ulonglong2*)&Wt2[k*16 + (g << 2) + 2];
            FMA2(acc[0], wa.x, hp.x); FMA2(acc[1], wa.x, hp.y);
            FMA2(acc[2], wa.y, hp.x); FMA2(acc[3], wa.y, hp.y);
            FMA2(acc[4], wb.x, hp.x); FMA2(acc[5], wb.x, hp.y);
            FMA2(acc[6], wb.y, hp.x); FMA2(acc[7], wb.y, hp.y);
        }
        float hold = hs[(kh << 6) + eb];
#pragma unroll
        for (int u = 0; u < 4; u++) {
            float2 p0 = u64_as_f2(acc[u*2 + 0]);
            float2 p1 = u64_as_f2(acc[u*2 + 1]);
            *(float4*)&Pf[kq*1024 + ((g << 2) + u)*64 + (btile << 2)] =
                make_float4(p0.x, p0.y, p1.x, p1.y);
        }
        __syncthreads();

        float s0 = Pf[eu*64+eb]      + Pf[1024 + eu*64+eb]      + Pf[2048 + eu*64+eb]      + Pf[3072 + eu*64+eb];
        float s1 = Pf[(4+eu)*64+eb]  + Pf[1024 + (4+eu)*64+eb]  + Pf[2048 + (4+eu)*64+eb]  + Pf[3072 + (4+eu)*64+eb];
        float s2 = Pf[(8+eu)*64+eb]  + Pf[1024 + (8+eu)*64+eb]  + Pf[2048 + (8+eu)*64+eb]  + Pf[3072 + (8+eu)*64+eb];
        float s3 = Pf[(12+eu)*64+eb] + Pf[1024 + (12+eu)*64+eb] + Pf[2048 + (12+eu)*64+eb] + Pf[3072 + (12+eu)*64+eb];

        float i_ = sigf(s0 + xp0);
        float f_ = sigf(s1 + xp1);
        float g_ = tanhf(s2 + xp2);
        float o_ = sigf(s3 + xp3);
        float cn = f_*c_reg + i_*g_;
        float hn = o_*tanhf(cn);

        bool m = (tok != 0);
        float hw = m ? hn : hold;
        c_reg    = m ? cn : c_reg;

        d_hbuf[(size_t)(dir*2 + (cur^1)) * (H_*B_) + kh*64 + eb] = hw;
        d_HC[((size_t)t*512 + (dir << 8) + kh)*64 + eb] = m ? hn : 0.f;

        flag_barrier(dir, myid, s + 2);
    }
}

__global__ void emissions_kernel(const float* __restrict__ w_lin, const float* __restrict__ b_lin) {
    int idx = blockIdx.x * 256 + threadIdx.x;
    if (idx >= T_*B_*NTAG) return;
    int row = idx / NTAG;
    int n   = idx - row * NTAG;
    const float4* hr = (const float4*)(d_H2 + (size_t)row * 512);
    const float4* wr = (const float4*)(w_lin + (size_t)n * 512);
    float acc = 0.f;
#pragma unroll 8
    for (int k = 0; k < 128; k++) {
        float4 h = hr[k]; float4 w = wr[k];
        acc += h.x*w.x + h.y*w.y + h.z*w.z + h.w*w.w;
    }
    d_EM[idx] = acc + b_lin[n];
}

__global__ __launch_bounds__(64)
void viterbi_kernel(const int* __restrict__ x, const float* __restrict__ start,
                    const float* __restrict__ endt, const float* __restrict__ trans,
                    float* __restrict__ out) {
    const int b = blockIdx.x;
    const int tid = threadIdx.x;
    __shared__ float trans_s[NTAG*NTAG];
    __shared__ float score[NTAG];
    __shared__ unsigned char hist[T_-1][NTAG];

    for (int i = tid; i < NTAG*NTAG; i += 64) trans_s[i] = trans[i];
    if (tid < NTAG) score[tid] = start[tid] + d_EM[b*NTAG + tid];
    __syncthreads();

    for (int t = 1; t < T_; t++) {
        float nv = 0.f;
        if (tid < NTAG) {
            float em = d_EM[(t*64 + b)*NTAG + tid];
            float best = -3.402823466e38f;
            int a = 0;
#pragma unroll
            for (int p = 0; p < NTAG; p++) {
                float sv = score[p] + trans_s[p*NTAG + tid];
                if (sv > best) { best = sv; a = p; }
            }
            bool m = (x[t*64 + b] != 0);
            nv = m ? (best + em) : score[tid];
            hist[t-1][tid] = (unsigned char)(m ? a : tid);
        }
        __syncthreads();
        if (tid < NTAG) score[tid] = nv;
        __syncthreads();
    }

    if (tid == 0) {
        float best = -3.402823466e38f;
        int tag = 0;
        for (int n = 0; n < NTAG; n++) {
            float sv = score[n] + endt[n];
            if (sv > best) { best = sv; tag = n; }
        }
        for (int t = T_-1; t >= 1; t--) {
            out[t*64 + b] = (x[t*64 + b] != 0) ? (float)tag : 0.f;
            tag = hist[t-1][tag];
        }
        out[b] = (x[b] != 0) ? (float)tag : 0.f;
    }
}

extern "C" void kernel_launch(void* const* d_in, const int* in_sizes, int n_in,
                              void* d_out, int out_size) {
    const void* P[16];
    if (n_in >= 16 && in_sizes[0] == T_*B_ && in_sizes[2] == 30000*256) {
        for (int i = 0; i < 16; i++) P[i] = d_in[i];
    } else if (n_in >= 15 && in_sizes[0] == T_*B_ && in_sizes[1] == 30000*256) {
        P[0] = d_in[0]; P[1] = d_in[0];
        for (int i = 2; i < 16; i++) P[i] = d_in[i-1];
    } else {
        P[0]  = d_in[15]; P[1]  = d_in[7];  P[2]  = d_in[5];
        P[3]  = d_in[12]; P[4]  = d_in[10]; P[5]  = d_in[2];  P[6]  = d_in[0];
        P[7]  = d_in[13]; P[8]  = d_in[11]; P[9]  = d_in[3];  P[10] = d_in[1];
        P[11] = d_in[14]; P[12] = d_in[4];
        P[13] = d_in[8];  P[14] = d_in[6];  P[15] = d_in[9];
    }

    const int*   x      = (const int*)P[0];
    const float* embed  = (const float*)P[2];
    const float* w_ih0  = (const float*)P[3];
    const float* w_hh0  = (const float*)P[4];
    const float* b_ih0  = (const float*)P[5];
    const float* b_hh0  = (const float*)P[6];
    const float* w_ih1  = (const float*)P[7];
    const float* w_hh1  = (const float*)P[8];
    const float* b_ih1  = (const float*)P[9];
    const float* b_hh1  = (const float*)P[10];
    const float* w_lin  = (const float*)P[11];
    const float* b_lin  = (const float*)P[12];
    const float* startt = (const float*)P[13];
    const float* endt   = (const float*)P[14];
    const float* trans  = (const float*)P[15];
    float* out = (float*)d_out;

    const int SMEM_SCAN = 112 * 1024;
    cudaFuncSetAttribute(lstm_scan, cudaFuncAttributeMaxDynamicSharedMemorySize, SMEM_SCAN);

    embed_kernel<<<4096, 256>>>(x, embed);
    sgemm_bias<<<dim3(8, 128, 2), 256>>>(0, w_ih0, b_ih0, b_hh0, 256);
    lstm_scan<<<128, 256, SMEM_SCAN>>>(w_hh0, x);
    zero_flags<<<8, 256>>>();
    transpose_h<<<dim3(16, 256), 256>>>(0);
    sgemm_bias<<<dim3(8, 128, 2), 256>>>(1, w_ih1, b_ih1, b_hh1, 512);
    lstm_scan<<<128, 256, SMEM_SCAN>>>(w_hh1, x);
    zero_flags<<<8, 256>>>();
    transpose_h<<<dim3(16, 256), 256>>>(1);
    emissions_kernel<<<(T_*B_*NTAG + 255)/256, 256>>>(w_lin, b_lin);
    viterbi_kernel<<<64, 64>>>(x, startt, endt, trans, out);
}